// round 9
// baseline (speedup 1.0000x reference)
#include <cuda_runtime.h>
#include <cstdint>

#define NN 50000
#define EE 400000
#define BBATCH 8
#define NDIM 32
#define EDIM 16
#define HH 128
#define LL 3
#define BM 128
#define BK 16
#define EMW 132  // padded sH row stride (floats)

__device__ float g_h[(size_t)NN * HH];
__device__ float g_pa[(size_t)NN * HH];
__device__ float g_pb[(size_t)NN * HH];
__device__ float g_aggr[(size_t)NN * HH];
__device__ float g_wec[LL * EDIM * HH];
__device__ float g_b1e[LL * HH];
__device__ float g_w2frag[LL * 16 * 16 * 32 * 4];   // fragment-packed hi/lo W2
__device__ int   g_src[EE];
__device__ int   g_dst[EE];
__device__ int   g_batchv[NN];
__device__ float g_pooled[BBATCH * HH];
__device__ float g_counts[BBATCH];
__device__ int   g_is64;

__device__ __forceinline__ float tf32r(float v) {
    uint32_t u;
    asm("cvt.rna.tf32.f32 %0, %1;" : "=r"(u) : "f"(v));
    return __uint_as_float(u);
}
__device__ __forceinline__ void mma8(float* c, const uint32_t* a, uint32_t b0, uint32_t b1) {
    asm volatile(
        "mma.sync.aligned.m16n8k8.row.col.f32.tf32.tf32.f32 "
        "{%0,%1,%2,%3}, {%4,%5,%6,%7}, {%8,%9}, {%0,%1,%2,%3};"
        : "+f"(c[0]), "+f"(c[1]), "+f"(c[2]), "+f"(c[3])
        : "r"(a[0]), "r"(a[1]), "r"(a[2]), "r"(a[3]), "r"(b0), "r"(b1));
}

// ---- setup ----
__global__ void detect_kernel(const unsigned int* __restrict__ ei) {
    int ok = 1;
    for (int i = 0; i < 256; i++)
        if (ei[2 * i + 1] != 0u) { ok = 0; break; }
    g_is64 = ok;
}

__global__ void convert_kernel(const void* __restrict__ ei, const void* __restrict__ bt) {
    const int is64 = g_is64;
    int i = blockIdx.x * blockDim.x + threadIdx.x;
    int stride = gridDim.x * blockDim.x;
    for (int k = i; k < EE; k += stride) {
        if (is64) {
            g_src[k] = (int)((const long long*)ei)[k];
            g_dst[k] = (int)((const long long*)ei)[EE + k];
        } else {
            g_src[k] = ((const int*)ei)[k];
            g_dst[k] = ((const int*)ei)[EE + k];
        }
    }
    for (int k = i; k < NN; k += stride)
        g_batchv[k] = is64 ? (int)((const long long*)bt)[k] : ((const int*)bt)[k];
}

__global__ void node_embed_kernel(const float* __restrict__ x,
                                  const float* __restrict__ Wn,
                                  const float* __restrict__ bn) {
    __shared__ float sW[NDIM * HH];
    __shared__ float sb[HH];
    for (int i = threadIdx.x; i < NDIM * HH; i += blockDim.x) sW[i] = Wn[i];
    if (threadIdx.x < HH) sb[threadIdx.x] = bn[threadIdx.x];
    __syncthreads();
    int g = blockIdx.x * blockDim.x + threadIdx.x;
    int stride = gridDim.x * blockDim.x;
    const int total = NN * 32;
    for (; g < total; g += stride) {
        int n = g >> 5;
        int c = (g & 31) * 4;
        const float* xr = x + (size_t)n * NDIM;
        float4 o = make_float4(sb[c], sb[c + 1], sb[c + 2], sb[c + 3]);
#pragma unroll
        for (int k = 0; k < NDIM; k++) {
            float a = __ldg(xr + k);
            float4 w = *(const float4*)&sW[k * HH + c];
            o.x = fmaf(a, w.x, o.x); o.y = fmaf(a, w.y, o.y);
            o.z = fmaf(a, w.z, o.z); o.w = fmaf(a, w.w, o.w);
        }
        *(float4*)&g_h[(size_t)n * HH + c] = o;
    }
}

// grid (LL, 17), block 128: d<16 -> Wec row; d==16 -> b1e
__global__ void fuse_wec_kernel(const float* __restrict__ We,
                                const float* __restrict__ be,
                                const float* __restrict__ mW1,
                                const float* __restrict__ mb1) {
    __shared__ float srow[HH];
    const int l = blockIdx.x;
    const int d = blockIdx.y;
    const float* W1c = mW1 + (size_t)l * 3 * HH * HH + 2 * HH * HH;
    const int c = threadIdx.x;
    srow[c] = (d < EDIM) ? We[d * HH + c] : be[c];
    __syncthreads();
    float s = (d < EDIM) ? 0.f : mb1[l * HH + c];
    for (int j = 0; j < HH; j++)
        s = fmaf(srow[j], W1c[j * HH + c], s);
    if (d < EDIM) g_wec[(size_t)l * EDIM * HH + d * HH + c] = s;
    else          g_b1e[l * HH + c] = s;
}

// Pack W2 into mma.sync B-fragment order, tf32 hi/lo interleaved.
// grid (LL, 16), block 512:  entry (kc, nt, lane) -> float4 {b0hi,b1hi,b0lo,b1lo}
__global__ void w2frag_prep_kernel(const float* __restrict__ mW2) {
    const int l = blockIdx.x, kc = blockIdx.y;
    const float* W2 = mW2 + (size_t)l * HH * HH;
    const int t = threadIdx.x;
    const int nt = t >> 5, lane = t & 31;
    const int kr0 = kc * 8 + (lane & 3);
    const int col = nt * 8 + (lane >> 2);
    float b0 = W2[kr0 * HH + col];
    float b1 = W2[(kr0 + 4) * HH + col];
    float b0h = tf32r(b0), b1h = tf32r(b1);
    float4 v = make_float4(b0h, b1h, tf32r(b0 - b0h), tf32r(b1 - b1h));
    ((float4*)g_w2frag)[((size_t)l * 256 + kc * 16 + nt) * 32 + lane] = v;
}

__global__ __launch_bounds__(256)
void pa_pb_kernel(const float* __restrict__ W1) {
    __shared__ float sA[BK * BM];
    __shared__ float sB[BK * HH];
    const int tid = threadIdx.x;
    const int nbase = blockIdx.x * BM;
    const int tx = tid & 15;
    const int ty = tid >> 4;
    const int r_g = tid >> 1;
    const int kq = (tid & 1) * 8;
    int gnode = nbase + r_g;
    if (gnode >= NN) gnode = NN - 1;
    const float* bp = g_h + (size_t)gnode * HH;
    const float* wb = W1 + (size_t)blockIdx.y * HH * HH;
    float* outp = blockIdx.y ? g_pb : g_pa;

    float acc[8][8];
#pragma unroll
    for (int i = 0; i < 8; i++)
#pragma unroll
        for (int j = 0; j < 8; j++) acc[i][j] = 0.f;
    const int wkr = (tid * 2) >> 5;
    const int wc4 = ((tid * 2) & 31) * 4;

#pragma unroll 1
    for (int kt = 0; kt < HH; kt += BK) {
        float4 v0 = *(const float4*)(bp + kt + kq);
        float4 v1 = *(const float4*)(bp + kt + kq + 4);
        sA[(kq + 0) * BM + r_g] = v0.x; sA[(kq + 1) * BM + r_g] = v0.y;
        sA[(kq + 2) * BM + r_g] = v0.z; sA[(kq + 3) * BM + r_g] = v0.w;
        sA[(kq + 4) * BM + r_g] = v1.x; sA[(kq + 5) * BM + r_g] = v1.y;
        sA[(kq + 6) * BM + r_g] = v1.z; sA[(kq + 7) * BM + r_g] = v1.w;
        const float* wp = wb + (size_t)(kt + wkr) * HH + wc4;
        *(float4*)&sB[wkr * HH + wc4]     = *(const float4*)wp;
        *(float4*)&sB[wkr * HH + wc4 + 4] = *(const float4*)(wp + 4);
        __syncthreads();
#pragma unroll
        for (int k = 0; k < BK; k++) {
            float4 a0 = *(float4*)&sA[k * BM + ty * 4];
            float4 a1 = *(float4*)&sA[k * BM + 64 + ty * 4];
            float4 bb0 = *(float4*)&sB[k * HH + tx * 4];
            float4 bb1 = *(float4*)&sB[k * HH + 64 + tx * 4];
            float a[8] = {a0.x, a0.y, a0.z, a0.w, a1.x, a1.y, a1.z, a1.w};
            float b[8] = {bb0.x, bb0.y, bb0.z, bb0.w, bb1.x, bb1.y, bb1.z, bb1.w};
#pragma unroll
            for (int i = 0; i < 8; i++)
#pragma unroll
                for (int j = 0; j < 8; j++)
                    acc[i][j] = fmaf(a[i], b[j], acc[i][j]);
        }
        __syncthreads();
    }
#pragma unroll
    for (int i = 0; i < 8; i++) {
        int r = (i < 4) ? (ty * 4 + i) : (64 + ty * 4 + (i - 4));
        int node = nbase + r;
        if (node < NN) {
            float* op = outp + (size_t)node * HH;
            *(float4*)(op + tx * 4) = make_float4(acc[i][0], acc[i][1], acc[i][2], acc[i][3]);
            *(float4*)(op + 64 + tx * 4) = make_float4(acc[i][4], acc[i][5], acc[i][6], acc[i][7]);
        }
    }
}

__global__ void zero_aggr_kernel() {
    int i = blockIdx.x * blockDim.x + threadIdx.x;
    int stride = gridDim.x * blockDim.x;
    float4 z = make_float4(0.f, 0.f, 0.f, 0.f);
    const int n4 = NN * HH / 4;
    for (int k = i; k < n4; k += stride) ((float4*)g_aggr)[k] = z;
}

__global__ void zero_pool_kernel() {
    for (int k = threadIdx.x; k < BBATCH * HH; k += blockDim.x) g_pooled[k] = 0.f;
    if (threadIdx.x < BBATCH) g_counts[threadIdx.x] = 0.f;
}

// ---- edge MLP v4: FFMA phase-1 + mma.sync tf32x3 phase-2 ----
// smem floats: sH[128*132] | sW2[32768] | sEA[2048] | sWec[2048] | sB1e[128] | sB2[128] | idx[256]
#define SH_F   0
#define SW2_F  (128 * EMW)
#define SEA_F  (SW2_F + 32768)
#define SWEC_F (SEA_F + 2048)
#define SB1E_F (SWEC_F + 2048)
#define SB2_F  (SB1E_F + 128)
#define IDX_F  (SB2_F + 128)
#define EK4_FLOATS (IDX_F + 256)
#define EK4_BYTES (EK4_FLOATS * 4)

__global__ __launch_bounds__(256, 1)
void edge_mlp4_kernel(const float* __restrict__ ea, int l,
                      const float* __restrict__ b2v) {
    extern __shared__ float sm[];
    float* sH = sm + SH_F;
    float* sW2 = sm + SW2_F;
    float* sEA = sm + SEA_F;
    float* sWec = sm + SWEC_F;
    float* sB1e = sm + SB1E_F;
    float* sB2 = sm + SB2_F;
    int* sDst = (int*)(sm + IDX_F);
    int* sSrc = sDst + BM;

    const int tid = threadIdx.x;
    const int ebase = blockIdx.x * BM;

    if (tid < BM) sDst[tid] = g_dst[ebase + tid];
    else          sSrc[tid - BM] = g_src[ebase + tid - BM];
    {
        const float4* s4 = (const float4*)(ea + (size_t)ebase * EDIM);
        ((float4*)sEA)[tid] = s4[tid];
        ((float4*)sEA)[tid + 256] = s4[tid + 256];
        const float4* w4 = (const float4*)(g_wec + (size_t)l * EDIM * HH);
        ((float4*)sWec)[tid] = w4[tid];
        ((float4*)sWec)[tid + 256] = w4[tid + 256];
    }
    if (tid < HH) {
        sB1e[tid] = g_b1e[l * HH + tid];
        sB2[tid] = b2v[tid];
    }
    __syncthreads();

    // ---- phase 1: hidden = relu(Pa[dst]+Pb[src]+ea@Wec+b1e) -> sH row-major ----
    {
        const int r = tid >> 1;
        const int cb = (tid & 1) * 64;
        const float* pa = g_pa + (size_t)sDst[r] * HH + cb;
        const float* pb = g_pb + (size_t)sSrc[r] * HH + cb;
        float eav[16];
#pragma unroll
        for (int k = 0; k < 16; k++) eav[k] = sEA[r * EDIM + k];
#pragma unroll 4
        for (int c0 = 0; c0 < 64; c0 += 4) {
            float4 a = *(const float4*)(pa + c0);
            float4 b = *(const float4*)(pb + c0);
            float4 bb = *(const float4*)(sB1e + cb + c0);
            float sx = a.x + b.x + bb.x;
            float sy = a.y + b.y + bb.y;
            float sz = a.z + b.z + bb.z;
            float sw = a.w + b.w + bb.w;
#pragma unroll
            for (int k = 0; k < 16; k++) {
                float4 w = *(const float4*)&sWec[k * HH + cb + c0];
                sx = fmaf(eav[k], w.x, sx);
                sy = fmaf(eav[k], w.y, sy);
                sz = fmaf(eav[k], w.z, sz);
                sw = fmaf(eav[k], w.w, sw);
            }
            float4 o;
            o.x = fmaxf(sx, 0.f); o.y = fmaxf(sy, 0.f);
            o.z = fmaxf(sz, 0.f); o.w = fmaxf(sw, 0.f);
            *(float4*)&sH[r * EMW + cb + c0] = o;
        }
    }

    // stage W2 fragments (128 KB) into smem
    {
        const float4* wsrc = (const float4*)(g_w2frag + (size_t)l * 32768);
        float4* wdst = (float4*)sW2;
#pragma unroll 4
        for (int i = tid; i < 8192; i += 256) wdst[i] = wsrc[i];
    }
    __syncthreads();

    // ---- phase 2: D = hidden @ W2 via tf32x3 mma.sync ----
    const int lane = tid & 31;
    const int wid = tid >> 5;
    const int r0 = wid * 16 + (lane >> 2);

    float acc[16][4];
#pragma unroll
    for (int nt = 0; nt < 16; nt++)
#pragma unroll
        for (int q = 0; q < 4; q++) acc[nt][q] = 0.f;

    const float4* w4 = (const float4*)sW2;
#pragma unroll 1
    for (int kc = 0; kc < 16; kc++) {
        const int k0 = kc * 8 + (lane & 3);
        float a0 = sH[r0 * EMW + k0];
        float a1 = sH[(r0 + 8) * EMW + k0];
        float a2 = sH[r0 * EMW + k0 + 4];
        float a3 = sH[(r0 + 8) * EMW + k0 + 4];
        float h0 = tf32r(a0), h1 = tf32r(a1), h2 = tf32r(a2), h3 = tf32r(a3);
        uint32_t ah[4] = {__float_as_uint(h0), __float_as_uint(h1),
                          __float_as_uint(h2), __float_as_uint(h3)};
        uint32_t al[4] = {__float_as_uint(tf32r(a0 - h0)), __float_as_uint(tf32r(a1 - h1)),
                          __float_as_uint(tf32r(a2 - h2)), __float_as_uint(tf32r(a3 - h3))};
#pragma unroll
        for (int nt = 0; nt < 16; nt++) {
            float4 bq = w4[(kc * 16 + nt) * 32 + lane];
            uint32_t bh0 = __float_as_uint(bq.x), bh1 = __float_as_uint(bq.y);
            uint32_t bl0 = __float_as_uint(bq.z), bl1 = __float_as_uint(bq.w);
            mma8(acc[nt], ah, bh0, bh1);
            mma8(acc[nt], al, bh0, bh1);
            mma8(acc[nt], ah, bl0, bl1);
        }
    }

    __syncthreads();   // everyone done reading sH

    // D -> sH row-major
#pragma unroll
    for (int nt = 0; nt < 16; nt++) {
        int c = nt * 8 + 2 * (lane & 3);
        *(float2*)&sH[r0 * EMW + c] = make_float2(acc[nt][0], acc[nt][1]);
        *(float2*)&sH[(r0 + 8) * EMW + c] = make_float2(acc[nt][2], acc[nt][3]);
    }
    __syncthreads();

    // scatter: aggr[dst] += D + b2 (vector reductions, proven path)
    {
        const int rr = tid >> 1;
        const int hb = (tid & 1) * 64;
        float* op = g_aggr + (size_t)sDst[rr] * HH + hb;
        const float* hrow = sH + rr * EMW + hb;
        const float* b2 = sB2 + hb;
#pragma unroll
        for (int c = 0; c < 64; c += 4) {
            float4 v = *(const float4*)(hrow + c);
            float4 b = *(const float4*)(b2 + c);
            float vx = v.x + b.x, vy = v.y + b.y, vz = v.z + b.z, vw = v.w + b.w;
            asm volatile("red.global.add.v4.f32 [%0], {%1, %2, %3, %4};"
                         :: "l"(op + c), "f"(vx), "f"(vy), "f"(vz), "f"(vw)
                         : "memory");
        }
    }
}

// ---- node update (FFMA) ----
__global__ __launch_bounds__(256, 2)
void node_mlp_kernel(const float* __restrict__ W1, const float* __restrict__ b1v,
                     const float* __restrict__ W2, const float* __restrict__ b2v) {
    extern __shared__ float nsm[];
    float* sA = nsm;
    float* sB = sA + BK * BM;
    float* sH = sB + BK * HH;
    const int tid = threadIdx.x;
    const int nbase = blockIdx.x * BM;
    const int tx = tid & 15;
    const int ty = tid >> 4;
    const int r_g = tid >> 1;
    const int kq = (tid & 1) * 8;
    int gnode = nbase + r_g;
    if (gnode >= NN) gnode = NN - 1;
    const float* base0 = g_h + (size_t)gnode * HH;
    const float* base1 = g_aggr + (size_t)gnode * HH;

    float acc[8][8];
#pragma unroll
    for (int i = 0; i < 8; i++)
#pragma unroll
        for (int j = 0; j < 8; j++) acc[i][j] = 0.f;
    const int wkr = (tid * 2) >> 5;
    const int wc4 = ((tid * 2) & 31) * 4;

#pragma unroll 1
    for (int reg = 0; reg < 2; reg++) {
        const float* bp = (reg == 0) ? base0 : base1;
        const float* wb = W1 + (size_t)reg * HH * HH;
#pragma unroll 1
        for (int kt = 0; kt < HH; kt += BK) {
            float4 v0 = *(const float4*)(bp + kt + kq);
            float4 v1 = *(const float4*)(bp + kt + kq + 4);
            sA[(kq + 0) * BM + r_g] = v0.x; sA[(kq + 1) * BM + r_g] = v0.y;
            sA[(kq + 2) * BM + r_g] = v0.z; sA[(kq + 3) * BM + r_g] = v0.w;
            sA[(kq + 4) * BM + r_g] = v1.x; sA[(kq + 5) * BM + r_g] = v1.y;
            sA[(kq + 6) * BM + r_g] = v1.z; sA[(kq + 7) * BM + r_g] = v1.w;
            const float* wp = wb + (size_t)(kt + wkr) * HH + wc4;
            *(float4*)&sB[wkr * HH + wc4]     = *(const float4*)wp;
            *(float4*)&sB[wkr * HH + wc4 + 4] = *(const float4*)(wp + 4);
            __syncthreads();
#pragma unroll
            for (int k = 0; k < BK; k++) {
                float4 a0 = *(float4*)&sA[k * BM + ty * 4];
                float4 a1 = *(float4*)&sA[k * BM + 64 + ty * 4];
                float4 bb0 = *(float4*)&sB[k * HH + tx * 4];
                float4 bb1 = *(float4*)&sB[k * HH + 64 + tx * 4];
                float a[8] = {a0.x, a0.y, a0.z, a0.w, a1.x, a1.y, a1.z, a1.w};
                float b[8] = {bb0.x, bb0.y, bb0.z, bb0.w, bb1.x, bb1.y, bb1.z, bb1.w};
#pragma unroll
                for (int i = 0; i < 8; i++)
#pragma unroll
                    for (int j = 0; j < 8; j++)
                        acc[i][j] = fmaf(a[i], b[j], acc[i][j]);
            }
            __syncthreads();
        }
    }
#pragma unroll
    for (int j = 0; j < 8; j++) {
        int c = (j < 4) ? (tx * 4 + j) : (64 + tx * 4 + (j - 4));
        float bb = b1v[c];
#pragma unroll
        for (int i = 0; i < 8; i++) {
            int r = (i < 4) ? (ty * 4 + i) : (64 + ty * 4 + (i - 4));
            float v = acc[i][j] + bb;
            sH[c * BM + r] = (v > 0.f) ? v : 0.f;
            acc[i][j] = 0.f;
        }
    }
    __syncthreads();
#pragma unroll 1
    for (int kt = 0; kt < HH; kt += BK) {
        const float* wp = W2 + (size_t)(kt + wkr) * HH + wc4;
        *(float4*)&sB[wkr * HH + wc4]     = *(const float4*)wp;
        *(float4*)&sB[wkr * HH + wc4 + 4] = *(const float4*)(wp + 4);
        __syncthreads();
#pragma unroll
        for (int k = 0; k < BK; k++) {
            float4 a0 = *(float4*)&sH[(kt + k) * BM + ty * 4];
            float4 a1 = *(float4*)&sH[(kt + k) * BM + 64 + ty * 4];
            float4 bb0 = *(float4*)&sB[k * HH + tx * 4];
            float4 bb1 = *(float4*)&sB[k * HH + 64 + tx * 4];
            float a[8] = {a0.x, a0.y, a0.z, a0.w, a1.x, a1.y, a1.z, a1.w};
            float b[8] = {bb0.x, bb0.y, bb0.z, bb0.w, bb1.x, bb1.y, bb1.z, bb1.w};
#pragma unroll
            for (int i = 0; i < 8; i++)
#pragma unroll
                for (int j = 0; j < 8; j++)
                    acc[i][j] = fmaf(a[i], b[j], acc[i][j]);
        }
        __syncthreads();
    }
    float bias2[8];
#pragma unroll
    for (int j = 0; j < 8; j++) {
        int c = (j < 4) ? (tx * 4 + j) : (64 + tx * 4 + (j - 4));
        bias2[j] = b2v[c];
    }
#pragma unroll
    for (int i = 0; i < 8; i++) {
        int r = (i < 4) ? (ty * 4 + i) : (64 + ty * 4 + (i - 4));
        int node = nbase + r;
        if (node < NN) {
            float* op = g_h + (size_t)node * HH;
#pragma unroll
            for (int j = 0; j < 8; j++) {
                int c = (j < 4) ? (tx * 4 + j) : (64 + tx * 4 + (j - 4));
                op[c] += acc[i][j] + bias2[j];
            }
        }
    }
}

__global__ void pool_kernel() {
    __shared__ float sp[BBATCH * HH];
    __shared__ float sc[BBATCH];
    for (int i = threadIdx.x; i < BBATCH * HH; i += blockDim.x) sp[i] = 0.f;
    if (threadIdx.x < BBATCH) sc[threadIdx.x] = 0.f;
    __syncthreads();
    int g = blockIdx.x * blockDim.x + threadIdx.x;
    int stride = gridDim.x * blockDim.x;
    const int total = NN * HH;
    for (int idx = g; idx < total; idx += stride) {
        int n = idx >> 7;
        int j = idx & 127;
        int b = g_batchv[n];
        atomicAdd(&sp[b * HH + j], g_h[idx]);
        if (j == 0) atomicAdd(&sc[b], 1.f);
    }
    __syncthreads();
    for (int i = threadIdx.x; i < BBATCH * HH; i += blockDim.x)
        atomicAdd(&g_pooled[i], sp[i]);
    if (threadIdx.x < BBATCH) atomicAdd(&g_counts[threadIdx.x], sc[threadIdx.x]);
}

__global__ void readout_kernel(const float* __restrict__ gf,
                               const float* __restrict__ Wg, const float* __restrict__ bg,
                               const float* __restrict__ rW1, const float* __restrict__ rb1,
                               const float* __restrict__ rW2, const float* __restrict__ rb2,
                               const float* __restrict__ rW3, const float* __restrict__ rb3,
                               float* __restrict__ out) {
    __shared__ float fin[BBATCH * 2 * HH];
    __shared__ float h1[BBATCH * HH];
    __shared__ float h2[BBATCH * 64];
    const int t = threadIdx.x;
    for (int idx = t; idx < BBATCH * 2 * HH; idx += blockDim.x) {
        int b = idx >> 8;
        int c = idx & 255;
        float v;
        if (c < HH) {
            float cnt = g_counts[b];
            if (cnt < 1.f) cnt = 1.f;
            v = g_pooled[b * HH + c] / cnt;
        } else {
            v = gf[b] * Wg[c - HH] + bg[c - HH];
        }
        fin[idx] = v;
    }
    __syncthreads();
    for (int idx = t; idx < BBATCH * HH; idx += blockDim.x) {
        int b = idx >> 7;
        int j = idx & 127;
        float s = rb1[j];
        for (int k = 0; k < 2 * HH; k++)
            s = fmaf(fin[b * 256 + k], rW1[k * HH + j], s);
        h1[idx] = (s > 0.f) ? s : 0.f;
    }
    __syncthreads();
    for (int idx = t; idx < BBATCH * 64; idx += blockDim.x) {
        int b = idx >> 6;
        int j = idx & 63;
        float s = rb2[j];
        for (int k = 0; k < HH; k++)
            s = fmaf(h1[b * HH + k], rW2[k * 64 + j], s);
        h2[idx] = (s > 0.f) ? s : 0.f;
    }
    __syncthreads();
    if (t < BBATCH) {
        float s = rb3[0];
        for (int k = 0; k < 64; k++)
            s = fmaf(h2[t * 64 + k], rW3[k], s);
        out[t] = s;
    }
}

// ---- host launcher ----
extern "C" void kernel_launch(void* const* d_in, const int* in_sizes, int n_in,
                              void* d_out, int out_size) {
    const float *x = 0, *ea = 0, *gf = 0;
    const void  *ei = 0, *bt = 0;
    const float *Wn = 0, *bn = 0, *We = 0, *be = 0, *Wg = 0, *bg = 0;
    const float *mW1 = 0, *mb1 = 0, *mW2 = 0, *mb2 = 0;
    const float *uW1 = 0, *ub1 = 0, *uW2 = 0, *ub2 = 0;
    const float *rW1 = 0, *rb1 = 0, *rW2 = 0, *rb2 = 0, *rW3 = 0, *rb3 = 0;
    int c128 = 0, c384 = 0, c49 = 0, c64 = 0;
    for (int i = 0; i < n_in; i++) {
        const void* p = d_in[i];
        switch (in_sizes[i]) {
            case 1600000: x = (const float*)p; break;
            case 6400000: ea = (const float*)p; break;
            case 8:       gf = (const float*)p; break;
            case 800000:  ei = p; break;
            case 50000:   bt = p; break;
            case 4096:    Wn = (const float*)p; break;
            case 2048:    We = (const float*)p; break;
            case 147456:  mW1 = (const float*)p; break;
            case 98304:   uW1 = (const float*)p; break;
            case 32768:   rW1 = (const float*)p; break;
            case 8192:    rW2 = (const float*)p; break;
            case 1:       rb3 = (const float*)p; break;
            case 128:
                if (c128 == 0) bn = (const float*)p;
                else if (c128 == 1) be = (const float*)p;
                else if (c128 == 2) Wg = (const float*)p;
                else if (c128 == 3) bg = (const float*)p;
                else rb1 = (const float*)p;
                c128++;
                break;
            case 384:
                if (c384 == 0) mb1 = (const float*)p;
                else if (c384 == 1) mb2 = (const float*)p;
                else if (c384 == 2) ub1 = (const float*)p;
                else ub2 = (const float*)p;
                c384++;
                break;
            case 49152:
                if (c49 == 0) mW2 = (const float*)p;
                else uW2 = (const float*)p;
                c49++;
                break;
            case 64:
                if (c64 == 0) rb2 = (const float*)p;
                else rW3 = (const float*)p;
                c64++;
                break;
            default: break;
        }
    }
    float* out = (float*)d_out;
    (void)out_size;

    const int SMEM_NODE = (BK * BM + BK * HH + HH * BM) * 4;
    cudaFuncSetAttribute(edge_mlp4_kernel, cudaFuncAttributeMaxDynamicSharedMemorySize, EK4_BYTES);
    cudaFuncSetAttribute(node_mlp_kernel, cudaFuncAttributeMaxDynamicSharedMemorySize, SMEM_NODE);

    detect_kernel<<<1, 1>>>((const unsigned int*)ei);
    convert_kernel<<<1024, 256>>>(ei, bt);
    node_embed_kernel<<<3200, 256>>>(x, Wn, bn);
    fuse_wec_kernel<<<dim3(LL, 17), 128>>>(We, be, mW1, mb1);
    w2frag_prep_kernel<<<dim3(LL, 16), 512>>>(mW2);

    const int NB_NODE = (NN + BM - 1) / BM;
    for (int l = 0; l < LL; l++) {
        pa_pb_kernel<<<dim3(NB_NODE, 2), 256>>>(mW1 + (size_t)l * 3 * HH * HH);
        zero_aggr_kernel<<<1600, 256>>>();
        edge_mlp4_kernel<<<EE / BM, 256, EK4_BYTES>>>(ea, l, mb2 + l * HH);
        node_mlp_kernel<<<NB_NODE, 256, SMEM_NODE>>>(
            uW1 + (size_t)l * 2 * HH * HH, ub1 + l * HH,
            uW2 + (size_t)l * HH * HH, ub2 + l * HH);
    }

    zero_pool_kernel<<<1, 256>>>();
    pool_kernel<<<1024, 256>>>();
    readout_kernel<<<1, 256>>>(gf, Wg, bg, rW1, rb1, rW2, rb2, rW3, rb3, out);
}

// round 10
// speedup vs baseline: 1.0562x; 1.0562x over previous
#include <cuda_runtime.h>
#include <cstdint>

#define NN 50000
#define EE 400000
#define BBATCH 8
#define NDIM 32
#define EDIM 16
#define HH 128
#define LL 3
#define BM 128
#define BK 16
#define EMW 132  // padded sH row stride (floats)

__device__ float g_h[(size_t)NN * HH];
__device__ float g_pa[(size_t)NN * HH];
__device__ float g_pb[(size_t)NN * HH];
__device__ float g_aggr[(size_t)NN * HH];
__device__ float g_wec[LL * EDIM * HH];
__device__ float g_b1e[LL * HH];
__device__ float g_w2frag[LL * 16 * 16 * 32 * 4];   // fragment-packed hi/lo W2
__device__ int   g_src[EE];
__device__ int   g_dst[EE];
__device__ int   g_batchv[NN];
__device__ float g_pooled[BBATCH * HH];
__device__ float g_counts[BBATCH];
__device__ int   g_is64;

__device__ __forceinline__ float tf32r(float v) {
    uint32_t u;
    asm("cvt.rna.tf32.f32 %0, %1;" : "=r"(u) : "f"(v));
    return __uint_as_float(u);
}
__device__ __forceinline__ void mma8(float* c, const uint32_t* a, uint32_t b0, uint32_t b1) {
    asm volatile(
        "mma.sync.aligned.m16n8k8.row.col.f32.tf32.tf32.f32 "
        "{%0,%1,%2,%3}, {%4,%5,%6,%7}, {%8,%9}, {%0,%1,%2,%3};"
        : "+f"(c[0]), "+f"(c[1]), "+f"(c[2]), "+f"(c[3])
        : "r"(a[0]), "r"(a[1]), "r"(a[2]), "r"(a[3]), "r"(b0), "r"(b1));
}

// ---- setup ----
__global__ void detect_kernel(const unsigned int* __restrict__ ei) {
    int ok = 1;
    for (int i = 0; i < 256; i++)
        if (ei[2 * i + 1] != 0u) { ok = 0; break; }
    g_is64 = ok;
}

__global__ void convert_kernel(const void* __restrict__ ei, const void* __restrict__ bt) {
    const int is64 = g_is64;
    int i = blockIdx.x * blockDim.x + threadIdx.x;
    int stride = gridDim.x * blockDim.x;
    for (int k = i; k < EE; k += stride) {
        if (is64) {
            g_src[k] = (int)((const long long*)ei)[k];
            g_dst[k] = (int)((const long long*)ei)[EE + k];
        } else {
            g_src[k] = ((const int*)ei)[k];
            g_dst[k] = ((const int*)ei)[EE + k];
        }
    }
    for (int k = i; k < NN; k += stride)
        g_batchv[k] = is64 ? (int)((const long long*)bt)[k] : ((const int*)bt)[k];
}

__global__ void node_embed_kernel(const float* __restrict__ x,
                                  const float* __restrict__ Wn,
                                  const float* __restrict__ bn) {
    __shared__ float sW[NDIM * HH];
    __shared__ float sb[HH];
    for (int i = threadIdx.x; i < NDIM * HH; i += blockDim.x) sW[i] = Wn[i];
    if (threadIdx.x < HH) sb[threadIdx.x] = bn[threadIdx.x];
    __syncthreads();
    int g = blockIdx.x * blockDim.x + threadIdx.x;
    int stride = gridDim.x * blockDim.x;
    const int total = NN * 32;
    for (; g < total; g += stride) {
        int n = g >> 5;
        int c = (g & 31) * 4;
        const float* xr = x + (size_t)n * NDIM;
        float4 o = make_float4(sb[c], sb[c + 1], sb[c + 2], sb[c + 3]);
#pragma unroll
        for (int k = 0; k < NDIM; k++) {
            float a = __ldg(xr + k);
            float4 w = *(const float4*)&sW[k * HH + c];
            o.x = fmaf(a, w.x, o.x); o.y = fmaf(a, w.y, o.y);
            o.z = fmaf(a, w.z, o.z); o.w = fmaf(a, w.w, o.w);
        }
        *(float4*)&g_h[(size_t)n * HH + c] = o;
    }
}

// grid (LL, 17), block 128
__global__ void fuse_wec_kernel(const float* __restrict__ We,
                                const float* __restrict__ be,
                                const float* __restrict__ mW1,
                                const float* __restrict__ mb1) {
    __shared__ float srow[HH];
    const int l = blockIdx.x;
    const int d = blockIdx.y;
    const float* W1c = mW1 + (size_t)l * 3 * HH * HH + 2 * HH * HH;
    const int c = threadIdx.x;
    srow[c] = (d < EDIM) ? We[d * HH + c] : be[c];
    __syncthreads();
    float s = (d < EDIM) ? 0.f : mb1[l * HH + c];
    for (int j = 0; j < HH; j++)
        s = fmaf(srow[j], W1c[j * HH + c], s);
    if (d < EDIM) g_wec[(size_t)l * EDIM * HH + d * HH + c] = s;
    else          g_b1e[l * HH + c] = s;
}

// Pack W2 into mma.sync B-fragment order, tf32 hi/lo interleaved.
__global__ void w2frag_prep_kernel(const float* __restrict__ mW2) {
    const int l = blockIdx.x, kc = blockIdx.y;
    const float* W2 = mW2 + (size_t)l * HH * HH;
    const int t = threadIdx.x;
    const int nt = t >> 5, lane = t & 31;
    const int kr0 = kc * 8 + (lane & 3);
    const int col = nt * 8 + (lane >> 2);
    float b0 = W2[kr0 * HH + col];
    float b1 = W2[(kr0 + 4) * HH + col];
    float b0h = tf32r(b0), b1h = tf32r(b1);
    float4 v = make_float4(b0h, b1h, tf32r(b0 - b0h), tf32r(b1 - b1h));
    ((float4*)g_w2frag)[((size_t)l * 256 + kc * 16 + nt) * 32 + lane] = v;
}

__global__ __launch_bounds__(256)
void pa_pb_kernel(const float* __restrict__ W1) {
    __shared__ float sA[BK * BM];
    __shared__ float sB[BK * HH];
    const int tid = threadIdx.x;
    const int nbase = blockIdx.x * BM;
    const int tx = tid & 15;
    const int ty = tid >> 4;
    const int r_g = tid >> 1;
    const int kq = (tid & 1) * 8;
    int gnode = nbase + r_g;
    if (gnode >= NN) gnode = NN - 1;
    const float* bp = g_h + (size_t)gnode * HH;
    const float* wb = W1 + (size_t)blockIdx.y * HH * HH;
    float* outp = blockIdx.y ? g_pb : g_pa;

    float acc[8][8];
#pragma unroll
    for (int i = 0; i < 8; i++)
#pragma unroll
        for (int j = 0; j < 8; j++) acc[i][j] = 0.f;
    const int wkr = (tid * 2) >> 5;
    const int wc4 = ((tid * 2) & 31) * 4;

#pragma unroll 1
    for (int kt = 0; kt < HH; kt += BK) {
        float4 v0 = *(const float4*)(bp + kt + kq);
        float4 v1 = *(const float4*)(bp + kt + kq + 4);
        sA[(kq + 0) * BM + r_g] = v0.x; sA[(kq + 1) * BM + r_g] = v0.y;
        sA[(kq + 2) * BM + r_g] = v0.z; sA[(kq + 3) * BM + r_g] = v0.w;
        sA[(kq + 4) * BM + r_g] = v1.x; sA[(kq + 5) * BM + r_g] = v1.y;
        sA[(kq + 6) * BM + r_g] = v1.z; sA[(kq + 7) * BM + r_g] = v1.w;
        const float* wp = wb + (size_t)(kt + wkr) * HH + wc4;
        *(float4*)&sB[wkr * HH + wc4]     = *(const float4*)wp;
        *(float4*)&sB[wkr * HH + wc4 + 4] = *(const float4*)(wp + 4);
        __syncthreads();
#pragma unroll
        for (int k = 0; k < BK; k++) {
            float4 a0 = *(float4*)&sA[k * BM + ty * 4];
            float4 a1 = *(float4*)&sA[k * BM + 64 + ty * 4];
            float4 bb0 = *(float4*)&sB[k * HH + tx * 4];
            float4 bb1 = *(float4*)&sB[k * HH + 64 + tx * 4];
            float a[8] = {a0.x, a0.y, a0.z, a0.w, a1.x, a1.y, a1.z, a1.w};
            float b[8] = {bb0.x, bb0.y, bb0.z, bb0.w, bb1.x, bb1.y, bb1.z, bb1.w};
#pragma unroll
            for (int i = 0; i < 8; i++)
#pragma unroll
                for (int j = 0; j < 8; j++)
                    acc[i][j] = fmaf(a[i], b[j], acc[i][j]);
        }
        __syncthreads();
    }
#pragma unroll
    for (int i = 0; i < 8; i++) {
        int r = (i < 4) ? (ty * 4 + i) : (64 + ty * 4 + (i - 4));
        int node = nbase + r;
        if (node < NN) {
            float* op = outp + (size_t)node * HH;
            *(float4*)(op + tx * 4) = make_float4(acc[i][0], acc[i][1], acc[i][2], acc[i][3]);
            *(float4*)(op + 64 + tx * 4) = make_float4(acc[i][4], acc[i][5], acc[i][6], acc[i][7]);
        }
    }
}

__global__ void zero_aggr_kernel() {
    int i = blockIdx.x * blockDim.x + threadIdx.x;
    int stride = gridDim.x * blockDim.x;
    float4 z = make_float4(0.f, 0.f, 0.f, 0.f);
    const int n4 = NN * HH / 4;
    for (int k = i; k < n4; k += stride) ((float4*)g_aggr)[k] = z;
}

__global__ void zero_pool_kernel() {
    for (int k = threadIdx.x; k < BBATCH * HH; k += blockDim.x) g_pooled[k] = 0.f;
    if (threadIdx.x < BBATCH) g_counts[threadIdx.x] = 0.f;
}

// ---- edge MLP v5: FFMA phase-1 + mma.sync tf32x3 phase-2, W2 frags via L1/L2 ----
// smem floats: sH[128*132] | sEA[2048] | sWec[2048] | sB1e[128] | sB2[128] | idx[256]
#define SH_F   0
#define SEA_F  (128 * EMW)
#define SWEC_F (SEA_F + 2048)
#define SB1E_F (SWEC_F + 2048)
#define SB2_F  (SB1E_F + 128)
#define IDX_F  (SB2_F + 128)
#define EK5_FLOATS (IDX_F + 256)
#define EK5_BYTES (EK5_FLOATS * 4)

__global__ __launch_bounds__(256, 2)
void edge_mlp5_kernel(const float* __restrict__ ea, int l,
                      const float* __restrict__ b2v) {
    extern __shared__ float sm[];
    float* sH = sm + SH_F;
    float* sEA = sm + SEA_F;
    float* sWec = sm + SWEC_F;
    float* sB1e = sm + SB1E_F;
    float* sB2 = sm + SB2_F;
    int* sDst = (int*)(sm + IDX_F);
    int* sSrc = sDst + BM;

    const int tid = threadIdx.x;
    const int ebase = blockIdx.x * BM;

    if (tid < BM) sDst[tid] = g_dst[ebase + tid];
    else          sSrc[tid - BM] = g_src[ebase + tid - BM];
    {
        const float4* s4 = (const float4*)(ea + (size_t)ebase * EDIM);
        ((float4*)sEA)[tid] = s4[tid];
        ((float4*)sEA)[tid + 256] = s4[tid + 256];
        const float4* w4 = (const float4*)(g_wec + (size_t)l * EDIM * HH);
        ((float4*)sWec)[tid] = w4[tid];
        ((float4*)sWec)[tid + 256] = w4[tid + 256];
    }
    if (tid < HH) {
        sB1e[tid] = g_b1e[l * HH + tid];
        sB2[tid] = b2v[tid];
    }
    __syncthreads();

    // ---- phase 1: hidden = relu(Pa[dst]+Pb[src]+ea@Wec+b1e) -> sH row-major ----
    {
        const int r = tid >> 1;
        const int cb = (tid & 1) * 64;
        const float* pa = g_pa + (size_t)sDst[r] * HH + cb;
        const float* pb = g_pb + (size_t)sSrc[r] * HH + cb;
        float eav[16];
#pragma unroll
        for (int k = 0; k < 16; k++) eav[k] = sEA[r * EDIM + k];
#pragma unroll 4
        for (int c0 = 0; c0 < 64; c0 += 4) {
            float4 a = *(const float4*)(pa + c0);
            float4 b = *(const float4*)(pb + c0);
            float4 bb = *(const float4*)(sB1e + cb + c0);
            float sx = a.x + b.x + bb.x;
            float sy = a.y + b.y + bb.y;
            float sz = a.z + b.z + bb.z;
            float sw = a.w + b.w + bb.w;
#pragma unroll
            for (int k = 0; k < 16; k++) {
                float4 w = *(const float4*)&sWec[k * HH + cb + c0];
                sx = fmaf(eav[k], w.x, sx);
                sy = fmaf(eav[k], w.y, sy);
                sz = fmaf(eav[k], w.z, sz);
                sw = fmaf(eav[k], w.w, sw);
            }
            float4 o;
            o.x = fmaxf(sx, 0.f); o.y = fmaxf(sy, 0.f);
            o.z = fmaxf(sz, 0.f); o.w = fmaxf(sw, 0.f);
            *(float4*)&sH[r * EMW + cb + c0] = o;
        }
    }
    __syncthreads();

    // ---- phase 2: D = hidden @ W2 via tf32x3 mma.sync; B frags from L1/L2 ----
    const int lane = tid & 31;
    const int wid = tid >> 5;
    const int r0 = wid * 16 + (lane >> 2);

    float acc[16][4];
#pragma unroll
    for (int nt = 0; nt < 16; nt++)
#pragma unroll
        for (int q = 0; q < 4; q++) acc[nt][q] = 0.f;

    const float4* w4 = (const float4*)(g_w2frag + (size_t)l * 32768);
#pragma unroll 1
    for (int kc = 0; kc < 16; kc++) {
        const int k0 = kc * 8 + (lane & 3);
        float a0 = sH[r0 * EMW + k0];
        float a1 = sH[(r0 + 8) * EMW + k0];
        float a2 = sH[r0 * EMW + k0 + 4];
        float a3 = sH[(r0 + 8) * EMW + k0 + 4];
        float h0 = tf32r(a0), h1 = tf32r(a1), h2 = tf32r(a2), h3 = tf32r(a3);
        uint32_t ah[4] = {__float_as_uint(h0), __float_as_uint(h1),
                          __float_as_uint(h2), __float_as_uint(h3)};
        uint32_t al[4] = {__float_as_uint(tf32r(a0 - h0)), __float_as_uint(tf32r(a1 - h1)),
                          __float_as_uint(tf32r(a2 - h2)), __float_as_uint(tf32r(a3 - h3))};
#pragma unroll
        for (int nt = 0; nt < 16; nt++) {
            float4 bq = __ldg(&w4[(kc * 16 + nt) * 32 + lane]);
            uint32_t bh0 = __float_as_uint(bq.x), bh1 = __float_as_uint(bq.y);
            uint32_t bl0 = __float_as_uint(bq.z), bl1 = __float_as_uint(bq.w);
            mma8(acc[nt], ah, bh0, bh1);
            mma8(acc[nt], al, bh0, bh1);
            mma8(acc[nt], ah, bl0, bl1);
        }
    }

    __syncthreads();   // everyone done reading sH

    // D -> sH row-major
#pragma unroll
    for (int nt = 0; nt < 16; nt++) {
        int c = nt * 8 + 2 * (lane & 3);
        *(float2*)&sH[r0 * EMW + c] = make_float2(acc[nt][0], acc[nt][1]);
        *(float2*)&sH[(r0 + 8) * EMW + c] = make_float2(acc[nt][2], acc[nt][3]);
    }
    __syncthreads();

    // scatter: aggr[dst] += D + b2
    {
        const int rr = tid >> 1;
        const int hb = (tid & 1) * 64;
        float* op = g_aggr + (size_t)sDst[rr] * HH + hb;
        const float* hrow = sH + rr * EMW + hb;
        const float* b2 = sB2 + hb;
#pragma unroll
        for (int c = 0; c < 64; c += 4) {
            float4 v = *(const float4*)(hrow + c);
            float4 b = *(const float4*)(b2 + c);
            float vx = v.x + b.x, vy = v.y + b.y, vz = v.z + b.z, vw = v.w + b.w;
            asm volatile("red.global.add.v4.f32 [%0], {%1, %2, %3, %4};"
                         :: "l"(op + c), "f"(vx), "f"(vy), "f"(vz), "f"(vw)
                         : "memory");
        }
    }
}

// ---- node update (FFMA) ----
__global__ __launch_bounds__(256, 2)
void node_mlp_kernel(const float* __restrict__ W1, const float* __restrict__ b1v,
                     const float* __restrict__ W2, const float* __restrict__ b2v) {
    extern __shared__ float nsm[];
    float* sA = nsm;
    float* sB = sA + BK * BM;
    float* sH = sB + BK * HH;
    const int tid = threadIdx.x;
    const int nbase = blockIdx.x * BM;
    const int tx = tid & 15;
    const int ty = tid >> 4;
    const int r_g = tid >> 1;
    const int kq = (tid & 1) * 8;
    int gnode = nbase + r_g;
    if (gnode >= NN) gnode = NN - 1;
    const float* base0 = g_h + (size_t)gnode * HH;
    const float* base1 = g_aggr + (size_t)gnode * HH;

    float acc[8][8];
#pragma unroll
    for (int i = 0; i < 8; i++)
#pragma unroll
        for (int j = 0; j < 8; j++) acc[i][j] = 0.f;
    const int wkr = (tid * 2) >> 5;
    const int wc4 = ((tid * 2) & 31) * 4;

#pragma unroll 1
    for (int reg = 0; reg < 2; reg++) {
        const float* bp = (reg == 0) ? base0 : base1;
        const float* wb = W1 + (size_t)reg * HH * HH;
#pragma unroll 1
        for (int kt = 0; kt < HH; kt += BK) {
            float4 v0 = *(const float4*)(bp + kt + kq);
            float4 v1 = *(const float4*)(bp + kt + kq + 4);
            sA[(kq + 0) * BM + r_g] = v0.x; sA[(kq + 1) * BM + r_g] = v0.y;
            sA[(kq + 2) * BM + r_g] = v0.z; sA[(kq + 3) * BM + r_g] = v0.w;
            sA[(kq + 4) * BM + r_g] = v1.x; sA[(kq + 5) * BM + r_g] = v1.y;
            sA[(kq + 6) * BM + r_g] = v1.z; sA[(kq + 7) * BM + r_g] = v1.w;
            const float* wp = wb + (size_t)(kt + wkr) * HH + wc4;
            *(float4*)&sB[wkr * HH + wc4]     = *(const float4*)wp;
            *(float4*)&sB[wkr * HH + wc4 + 4] = *(const float4*)(wp + 4);
            __syncthreads();
#pragma unroll
            for (int k = 0; k < BK; k++) {
                float4 a0 = *(float4*)&sA[k * BM + ty * 4];
                float4 a1 = *(float4*)&sA[k * BM + 64 + ty * 4];
                float4 bb0 = *(float4*)&sB[k * HH + tx * 4];
                float4 bb1 = *(float4*)&sB[k * HH + 64 + tx * 4];
                float a[8] = {a0.x, a0.y, a0.z, a0.w, a1.x, a1.y, a1.z, a1.w};
                float b[8] = {bb0.x, bb0.y, bb0.z, bb0.w, bb1.x, bb1.y, bb1.z, bb1.w};
#pragma unroll
                for (int i = 0; i < 8; i++)
#pragma unroll
                    for (int j = 0; j < 8; j++)
                        acc[i][j] = fmaf(a[i], b[j], acc[i][j]);
            }
            __syncthreads();
        }
    }
#pragma unroll
    for (int j = 0; j < 8; j++) {
        int c = (j < 4) ? (tx * 4 + j) : (64 + tx * 4 + (j - 4));
        float bb = b1v[c];
#pragma unroll
        for (int i = 0; i < 8; i++) {
            int r = (i < 4) ? (ty * 4 + i) : (64 + ty * 4 + (i - 4));
            float v = acc[i][j] + bb;
            sH[c * BM + r] = (v > 0.f) ? v : 0.f;
            acc[i][j] = 0.f;
        }
    }
    __syncthreads();
#pragma unroll 1
    for (int kt = 0; kt < HH; kt += BK) {
        const float* wp = W2 + (size_t)(kt + wkr) * HH + wc4;
        *(float4*)&sB[wkr * HH + wc4]     = *(const float4*)wp;
        *(float4*)&sB[wkr * HH + wc4 + 4] = *(const float4*)(wp + 4);
        __syncthreads();
#pragma unroll
        for (int k = 0; k < BK; k++) {
            float4 a0 = *(float4*)&sH[(kt + k) * BM + ty * 4];
            float4 a1 = *(float4*)&sH[(kt + k) * BM + 64 + ty * 4];
            float4 bb0 = *(float4*)&sB[k * HH + tx * 4];
            float4 bb1 = *(float4*)&sB[k * HH + 64 + tx * 4];
            float a[8] = {a0.x, a0.y, a0.z, a0.w, a1.x, a1.y, a1.z, a1.w};
            float b[8] = {bb0.x, bb0.y, bb0.z, bb0.w, bb1.x, bb1.y, bb1.z, bb1.w};
#pragma unroll
            for (int i = 0; i < 8; i++)
#pragma unroll
                for (int j = 0; j < 8; j++)
                    acc[i][j] = fmaf(a[i], b[j], acc[i][j]);
        }
        __syncthreads();
    }
    float bias2[8];
#pragma unroll
    for (int j = 0; j < 8; j++) {
        int c = (j < 4) ? (tx * 4 + j) : (64 + tx * 4 + (j - 4));
        bias2[j] = b2v[c];
    }
#pragma unroll
    for (int i = 0; i < 8; i++) {
        int r = (i < 4) ? (ty * 4 + i) : (64 + ty * 4 + (i - 4));
        int node = nbase + r;
        if (node < NN) {
            float* op = g_h + (size_t)node * HH;
#pragma unroll
            for (int j = 0; j < 8; j++) {
                int c = (j < 4) ? (tx * 4 + j) : (64 + tx * 4 + (j - 4));
                op[c] += acc[i][j] + bias2[j];
            }
        }
    }
}

__global__ void pool_kernel() {
    __shared__ float sp[BBATCH * HH];
    __shared__ float sc[BBATCH];
    for (int i = threadIdx.x; i < BBATCH * HH; i += blockDim.x) sp[i] = 0.f;
    if (threadIdx.x < BBATCH) sc[threadIdx.x] = 0.f;
    __syncthreads();
    int g = blockIdx.x * blockDim.x + threadIdx.x;
    int stride = gridDim.x * blockDim.x;
    const int total = NN * HH;
    for (int idx = g; idx < total; idx += stride) {
        int n = idx >> 7;
        int j = idx & 127;
        int b = g_batchv[n];
        atomicAdd(&sp[b * HH + j], g_h[idx]);
        if (j == 0) atomicAdd(&sc[b], 1.f);
    }
    __syncthreads();
    for (int i = threadIdx.x; i < BBATCH * HH; i += blockDim.x)
        atomicAdd(&g_pooled[i], sp[i]);
    if (threadIdx.x < BBATCH) atomicAdd(&g_counts[threadIdx.x], sc[threadIdx.x]);
}

__global__ void readout_kernel(const float* __restrict__ gf,
                               const float* __restrict__ Wg, const float* __restrict__ bg,
                               const float* __restrict__ rW1, const float* __restrict__ rb1,
                               const float* __restrict__ rW2, const float* __restrict__ rb2,
                               const float* __restrict__ rW3, const float* __restrict__ rb3,
                               float* __restrict__ out) {
    __shared__ float fin[BBATCH * 2 * HH];
    __shared__ float h1[BBATCH * HH];
    __shared__ float h2[BBATCH * 64];
    const int t = threadIdx.x;
    for (int idx = t; idx < BBATCH * 2 * HH; idx += blockDim.x) {
        int b = idx >> 8;
        int c = idx & 255;
        float v;
        if (c < HH) {
            float cnt = g_counts[b];
            if (cnt < 1.f) cnt = 1.f;
            v = g_pooled[b * HH + c] / cnt;
        } else {
            v = gf[b] * Wg[c - HH] + bg[c - HH];
        }
        fin[idx] = v;
    }
    __syncthreads();
    for (int idx = t; idx < BBATCH * HH; idx += blockDim.x) {
        int b = idx >> 7;
        int j = idx & 127;
        float s = rb1[j];
        for (int k = 0; k < 2 * HH; k++)
            s = fmaf(fin[b * 256 + k], rW1[k * HH + j], s);
        h1[idx] = (s > 0.f) ? s : 0.f;
    }
    __syncthreads();
    for (int idx = t; idx < BBATCH * 64; idx += blockDim.x) {
        int b = idx >> 6;
        int j = idx & 63;
        float s = rb2[j];
        for (int k = 0; k < HH; k++)
            s = fmaf(h1[b * HH + k], rW2[k * 64 + j], s);
        h2[idx] = (s > 0.f) ? s : 0.f;
    }
    __syncthreads();
    if (t < BBATCH) {
        float s = rb3[0];
        for (int k = 0; k < 64; k++)
            s = fmaf(h2[t * 64 + k], rW3[k], s);
        out[t] = s;
    }
}

// ---- host launcher ----
extern "C" void kernel_launch(void* const* d_in, const int* in_sizes, int n_in,
                              void* d_out, int out_size) {
    const float *x = 0, *ea = 0, *gf = 0;
    const void  *ei = 0, *bt = 0;
    const float *Wn = 0, *bn = 0, *We = 0, *be = 0, *Wg = 0, *bg = 0;
    const float *mW1 = 0, *mb1 = 0, *mW2 = 0, *mb2 = 0;
    const float *uW1 = 0, *ub1 = 0, *uW2 = 0, *ub2 = 0;
    const float *rW1 = 0, *rb1 = 0, *rW2 = 0, *rb2 = 0, *rW3 = 0, *rb3 = 0;
    int c128 = 0, c384 = 0, c49 = 0, c64 = 0;
    for (int i = 0; i < n_in; i++) {
        const void* p = d_in[i];
        switch (in_sizes[i]) {
            case 1600000: x = (const float*)p; break;
            case 6400000: ea = (const float*)p; break;
            case 8:       gf = (const float*)p; break;
            case 800000:  ei = p; break;
            case 50000:   bt = p; break;
            case 4096:    Wn = (const float*)p; break;
            case 2048:    We = (const float*)p; break;
            case 147456:  mW1 = (const float*)p; break;
            case 98304:   uW1 = (const float*)p; break;
            case 32768:   rW1 = (const float*)p; break;
            case 8192:    rW2 = (const float*)p; break;
            case 1:       rb3 = (const float*)p; break;
            case 128:
                if (c128 == 0) bn = (const float*)p;
                else if (c128 == 1) be = (const float*)p;
                else if (c128 == 2) Wg = (const float*)p;
                else if (c128 == 3) bg = (const float*)p;
                else rb1 = (const float*)p;
                c128++;
                break;
            case 384:
                if (c384 == 0) mb1 = (const float*)p;
                else if (c384 == 1) mb2 = (const float*)p;
                else if (c384 == 2) ub1 = (const float*)p;
                else ub2 = (const float*)p;
                c384++;
                break;
            case 49152:
                if (c49 == 0) mW2 = (const float*)p;
                else uW2 = (const float*)p;
                c49++;
                break;
            case 64:
                if (c64 == 0) rb2 = (const float*)p;
                else rW3 = (const float*)p;
                c64++;
                break;
            default: break;
        }
    }
    float* out = (float*)d_out;
    (void)out_size;

    const int SMEM_NODE = (BK * BM + BK * HH + HH * BM) * 4;
    cudaFuncSetAttribute(edge_mlp5_kernel, cudaFuncAttributeMaxDynamicSharedMemorySize, EK5_BYTES);
    cudaFuncSetAttribute(node_mlp_kernel, cudaFuncAttributeMaxDynamicSharedMemorySize, SMEM_NODE);

    detect_kernel<<<1, 1>>>((const unsigned int*)ei);
    convert_kernel<<<1024, 256>>>(ei, bt);
    node_embed_kernel<<<3200, 256>>>(x, Wn, bn);
    fuse_wec_kernel<<<dim3(LL, 17), 128>>>(We, be, mW1, mb1);
    w2frag_prep_kernel<<<dim3(LL, 16), 512>>>(mW2);

    const int NB_NODE = (NN + BM - 1) / BM;
    for (int l = 0; l < LL; l++) {
        pa_pb_kernel<<<dim3(NB_NODE, 2), 256>>>(mW1 + (size_t)l * 3 * HH * HH);
        zero_aggr_kernel<<<1600, 256>>>();
        edge_mlp5_kernel<<<EE / BM, 256, EK5_BYTES>>>(ea, l, mb2 + l * HH);
        node_mlp_kernel<<<NB_NODE, 256, SMEM_NODE>>>(
            uW1 + (size_t)l * 2 * HH * HH, ub1 + l * HH,
            uW2 + (size_t)l * HH * HH, ub2 + l * HH);
    }

    zero_pool_kernel<<<1, 256>>>();
    pool_kernel<<<1024, 256>>>();
    readout_kernel<<<1, 256>>>(gf, Wg, bg, rW1, rb1, rW2, rb2, rW3, rb3, out);
}